// round 2
// baseline (speedup 1.0000x reference)
#include <cuda_runtime.h>

#define N_NODES 100000
#define N_EDGES 200000
#define D_NODE 128
#define D_EDGE 16
#define N_REL 3

// Scratch: per-relation scattered sums.
// A_r[d,:] = sum_{e: dst=d} x[src_e,:]      (3 x 100000 x 128)  ~153.6 MB
// E_r[d,:] = sum_{e: dst=d} edge_attr[r,e]  (3 x 100000 x 16)   ~19.2 MB
__device__ float g_A[(size_t)N_REL * N_NODES * D_NODE];
__device__ float g_E[(size_t)N_REL * N_NODES * D_EDGE];

__global__ void zero_kernel() {
    const size_t nA = (size_t)N_REL * N_NODES * D_NODE / 4;
    const size_t nE = (size_t)N_REL * N_NODES * D_EDGE / 4;
    float4 z = make_float4(0.f, 0.f, 0.f, 0.f);
    float4* A4 = reinterpret_cast<float4*>(g_A);
    float4* E4 = reinterpret_cast<float4*>(g_E);
    size_t stride = (size_t)gridDim.x * blockDim.x;
    for (size_t i = (size_t)blockIdx.x * blockDim.x + threadIdx.x; i < nA; i += stride) A4[i] = z;
    for (size_t i = (size_t)blockIdx.x * blockDim.x + threadIdx.x; i < nE; i += stride) E4[i] = z;
}

// One warp per (relation, edge). 32 lanes x float4 = 128 floats of x[src]
// reduced into g_A[r][dst]; lanes 0-3 handle the 16-float edge_attr into g_E.
__global__ void scatter_kernel(const float* __restrict__ x,
                               const float* __restrict__ edge_attr,
                               const int*   __restrict__ edge_index) {
    int w = (blockIdx.x * blockDim.x + threadIdx.x) >> 5;
    int lane = threadIdx.x & 31;
    if (w >= N_REL * N_EDGES) return;
    int r = w / N_EDGES;
    int e = w - r * N_EDGES;

    int2 se = reinterpret_cast<const int2*>(edge_index)[w];  // {src, dst}
    int src = se.x, dst = se.y;

    const float4* xr = reinterpret_cast<const float4*>(x + (size_t)src * D_NODE);
    float4 v = xr[lane];
    float* a = g_A + ((size_t)r * N_NODES + dst) * D_NODE + lane * 4;
    asm volatile("red.global.add.v4.f32 [%0], {%1,%2,%3,%4};"
                 :: "l"(a), "f"(v.x), "f"(v.y), "f"(v.z), "f"(v.w) : "memory");

    if (lane < 4) {
        const float4* er = reinterpret_cast<const float4*>(
            edge_attr + ((size_t)r * N_EDGES + e) * D_EDGE);
        float4 u = er[lane];
        float* ep = g_E + ((size_t)r * N_NODES + dst) * D_EDGE + lane * 4;
        asm volatile("red.global.add.v4.f32 [%0], {%1,%2,%3,%4};"
                     :: "l"(ep), "f"(u.x), "f"(u.y), "f"(u.z), "f"(u.w) : "memory");
    }
}

// Fused GEMM: out = relu( x@W_self + sum_r A_r@W_rel[r] + sum_r E_r@We_rel[r] + b )
// Treated as M=100000, N=128, K = 128 + 3*128 + 3*16 = 560 (7 segments).
// 128x128 block tile, 256 threads, 8x8 per-thread register blocking, KC=16.
#define TM 128
#define TN 128
#define KC 16

__global__ __launch_bounds__(256, 2) void gemm_kernel(
    const float* __restrict__ x,
    const float* __restrict__ W_rel,
    const float* __restrict__ We_rel,
    const float* __restrict__ W_self,
    const float* __restrict__ bias,
    float* __restrict__ out) {
    __shared__ float As[TM * KC];   // As[m][k]
    __shared__ float Bs[KC * TN];   // Bs[k][n]

    int t = threadIdx.x;
    int m0 = blockIdx.x * TM;
    int tx = t & 15;        // n-dir: 16 threads x 8 cols = 128
    int ty = t >> 4;        // m-dir: 16 threads x 8 rows = 128

    float acc[8][8];
#pragma unroll
    for (int i = 0; i < 8; ++i)
#pragma unroll
        for (int j = 0; j < 8; ++j) acc[i][j] = 0.f;

    for (int seg = 0; seg < 7; ++seg) {
        const float* in;
        const float* W;
        int ld, Ks;
        if (seg == 0)      { in = x;                                       W = W_self;                       ld = D_NODE; Ks = D_NODE; }
        else if (seg < 4)  { int r = seg - 1;
                             in = g_A + (size_t)r * N_NODES * D_NODE;      W = W_rel + (size_t)r * D_NODE * D_NODE; ld = D_NODE; Ks = D_NODE; }
        else               { int r = seg - 4;
                             in = g_E + (size_t)r * N_NODES * D_EDGE;      W = We_rel + (size_t)r * D_EDGE * D_NODE; ld = D_EDGE; Ks = D_EDGE; }

        for (int kb = 0; kb < Ks; kb += KC) {
            // Load As: 128 rows x 16 k = 512 float4, 2 per thread
#pragma unroll
            for (int i = 0; i < 2; ++i) {
                int f = t + i * 256;
                int m = f >> 2, kq = f & 3;
                float4 v = make_float4(0.f, 0.f, 0.f, 0.f);
                if (m0 + m < N_NODES)
                    v = *reinterpret_cast<const float4*>(in + (size_t)(m0 + m) * ld + kb + kq * 4);
                *reinterpret_cast<float4*>(As + m * KC + kq * 4) = v;
            }
            // Load Bs: 16 k x 128 n = 512 float4, 2 per thread
#pragma unroll
            for (int i = 0; i < 2; ++i) {
                int f = t + i * 256;
                int kk = f >> 5, nq = f & 31;
                *reinterpret_cast<float4*>(Bs + kk * TN + nq * 4) =
                    *reinterpret_cast<const float4*>(W + (size_t)(kb + kk) * TN + nq * 4);
            }
            __syncthreads();

#pragma unroll
            for (int kk = 0; kk < KC; ++kk) {
                float a[8], bv[8];
#pragma unroll
                for (int i = 0; i < 8; ++i) a[i] = As[(ty * 8 + i) * KC + kk];
#pragma unroll
                for (int j = 0; j < 8; ++j) bv[j] = Bs[kk * TN + tx * 8 + j];
#pragma unroll
                for (int i = 0; i < 8; ++i)
#pragma unroll
                    for (int j = 0; j < 8; ++j) acc[i][j] = fmaf(a[i], bv[j], acc[i][j]);
            }
            __syncthreads();
        }
    }

    // Epilogue: + bias, relu, store
    float bb[8];
#pragma unroll
    for (int j = 0; j < 8; ++j) bb[j] = bias[tx * 8 + j];

#pragma unroll
    for (int i = 0; i < 8; ++i) {
        int row = m0 + ty * 8 + i;
        if (row < N_NODES) {
#pragma unroll
            for (int jq = 0; jq < 2; ++jq) {
                float4 v;
                v.x = fmaxf(acc[i][jq * 4 + 0] + bb[jq * 4 + 0], 0.f);
                v.y = fmaxf(acc[i][jq * 4 + 1] + bb[jq * 4 + 1], 0.f);
                v.z = fmaxf(acc[i][jq * 4 + 2] + bb[jq * 4 + 2], 0.f);
                v.w = fmaxf(acc[i][jq * 4 + 3] + bb[jq * 4 + 3], 0.f);
                *reinterpret_cast<float4*>(out + (size_t)row * 128 + tx * 8 + jq * 4) = v;
            }
        }
    }
}

extern "C" void kernel_launch(void* const* d_in, const int* in_sizes, int n_in,
                              void* d_out, int out_size) {
    const float* x         = (const float*)d_in[0];
    const float* edge_attr = (const float*)d_in[1];
    const float* W_rel     = (const float*)d_in[2];
    const float* We_rel    = (const float*)d_in[3];
    const float* W_self    = (const float*)d_in[4];
    const float* b         = (const float*)d_in[5];
    const int*   edge_index= (const int*)d_in[6];
    float* out = (float*)d_out;

    zero_kernel<<<2048, 256>>>();

    int n_warps = N_REL * N_EDGES;               // 600000 edge-warps
    int blocks = (n_warps * 32 + 255) / 256;     // 75000 blocks
    scatter_kernel<<<blocks, 256>>>(x, edge_attr, edge_index);

    int gblocks = (N_NODES + TM - 1) / TM;       // 782
    gemm_kernel<<<gblocks, 256>>>(x, W_rel, We_rel, W_self, b, out);
}

// round 4
// speedup vs baseline: 1.3716x; 1.3716x over previous
#include <cuda_runtime.h>
#include <cuda_bf16.h>
#include <cstdint>

#define N_NODES 100000
#define N_EDGES 200000
#define D_NODE 128
#define D_EDGE 16
#define N_REL 3

// ───────────────────────── scratch ─────────────────────────
__device__ float g_A[(size_t)N_REL * N_NODES * D_NODE];   // ~153.6 MB
__device__ float g_E[(size_t)N_REL * N_NODES * D_EDGE];   // ~19.2 MB

// ───────────────────────── zero + scatter (unchanged, known-good) ─────────────
__global__ void zero_kernel() {
    const size_t nA = (size_t)N_REL * N_NODES * D_NODE / 4;
    const size_t nE = (size_t)N_REL * N_NODES * D_EDGE / 4;
    float4 z = make_float4(0.f, 0.f, 0.f, 0.f);
    float4* A4 = reinterpret_cast<float4*>(g_A);
    float4* E4 = reinterpret_cast<float4*>(g_E);
    size_t stride = (size_t)gridDim.x * blockDim.x;
    for (size_t i = (size_t)blockIdx.x * blockDim.x + threadIdx.x; i < nA; i += stride) A4[i] = z;
    for (size_t i = (size_t)blockIdx.x * blockDim.x + threadIdx.x; i < nE; i += stride) E4[i] = z;
}

__global__ void scatter_kernel(const float* __restrict__ x,
                               const float* __restrict__ edge_attr,
                               const int*   __restrict__ edge_index) {
    int w = (blockIdx.x * blockDim.x + threadIdx.x) >> 5;
    int lane = threadIdx.x & 31;
    if (w >= N_REL * N_EDGES) return;
    int r = w / N_EDGES;
    int e = w - r * N_EDGES;

    int2 se = reinterpret_cast<const int2*>(edge_index)[w];
    int src = se.x, dst = se.y;

    const float4* xr = reinterpret_cast<const float4*>(x + (size_t)src * D_NODE);
    float4 v = xr[lane];
    float* a = g_A + ((size_t)r * N_NODES + dst) * D_NODE + lane * 4;
    asm volatile("red.global.add.v4.f32 [%0], {%1,%2,%3,%4};"
                 :: "l"(a), "f"(v.x), "f"(v.y), "f"(v.z), "f"(v.w) : "memory");

    if (lane < 4) {
        const float4* er = reinterpret_cast<const float4*>(
            edge_attr + ((size_t)r * N_EDGES + e) * D_EDGE);
        float4 u = er[lane];
        float* ep = g_E + ((size_t)r * N_NODES + dst) * D_EDGE + lane * 4;
        asm volatile("red.global.add.v4.f32 [%0], {%1,%2,%3,%4};"
                     :: "l"(ep), "f"(u.x), "f"(u.y), "f"(u.z), "f"(u.w) : "memory");
    }
}

// ───────────────────────── bf16x3 GEMM via mma.sync (HMMA) ─────────────────────
// out = relu( [x | A_0..A_2 | E_0..E_2] @ [W_self; W_rel; We_rel] + b )
// 11 K-chunks: 2 (x, K=64) + 6 (A_r, K=64) + 3 (E_r, K=16).
// D = Ah*Bh + Al*Bh + Ah*Bl  (fp32 accum; drops lo*lo term, err ~2^-17)

// split 8 fp32 -> 8 bf16 hi + 8 bf16 lo (packed as uint4 each)
__device__ __forceinline__ void split8(const float* f, uint4& hi, uint4& lo) {
    uint32_t h[8], l[8];
#pragma unroll
    for (int j = 0; j < 8; ++j) {
        __nv_bfloat16 hb = __float2bfloat16_rn(f[j]);
        float r = f[j] - __bfloat162float(hb);
        __nv_bfloat16 lb = __float2bfloat16_rn(r);
        h[j] = (uint32_t)__bfloat16_as_ushort(hb);
        l[j] = (uint32_t)__bfloat16_as_ushort(lb);
    }
    hi.x = h[0] | (h[1] << 16); hi.y = h[2] | (h[3] << 16);
    hi.z = h[4] | (h[5] << 16); hi.w = h[6] | (h[7] << 16);
    lo.x = l[0] | (l[1] << 16); lo.y = l[2] | (l[3] << 16);
    lo.z = l[4] | (l[5] << 16); lo.w = l[6] | (l[7] << 16);
}

__device__ __forceinline__ void mma16816(float* c, uint32_t a0, uint32_t a1,
                                         uint32_t a2, uint32_t a3,
                                         uint32_t b0, uint32_t b1) {
    asm volatile(
        "mma.sync.aligned.m16n8k16.row.col.f32.bf16.bf16.f32 "
        "{%0,%1,%2,%3}, {%4,%5,%6,%7}, {%8,%9}, {%0,%1,%2,%3};"
        : "+f"(c[0]), "+f"(c[1]), "+f"(c[2]), "+f"(c[3])
        : "r"(a0), "r"(a1), "r"(a2), "r"(a3), "r"(b0), "r"(b1));
}

// smem: bf16, padded k-stride 72 (144 B) -> 4-bank rotation per row, conflict-free
#define KPAD 72
static constexpr int TILE_B = 128 * KPAD * 2;           // 18432 bytes
static constexpr int OFF_AH = 0;
static constexpr int OFF_AL = OFF_AH + TILE_B;
static constexpr int OFF_BH = OFF_AL + TILE_B;
static constexpr int OFF_BL = OFF_BH + TILE_B;
static constexpr int SMEM_TOTAL = OFF_BL + TILE_B;      // 73728 bytes

__global__ __launch_bounds__(256) void gemm_mma_kernel(
    const float* __restrict__ x,
    const float* __restrict__ W_rel,
    const float* __restrict__ We_rel,
    const float* __restrict__ W_self,
    const float* __restrict__ bias,
    float* __restrict__ out) {
    extern __shared__ char smem[];
    __nv_bfloat16* sAH = reinterpret_cast<__nv_bfloat16*>(smem + OFF_AH);
    __nv_bfloat16* sAL = reinterpret_cast<__nv_bfloat16*>(smem + OFF_AL);
    __nv_bfloat16* sBH = reinterpret_cast<__nv_bfloat16*>(smem + OFF_BH);
    __nv_bfloat16* sBL = reinterpret_cast<__nv_bfloat16*>(smem + OFF_BL);

    int t = threadIdx.x;
    int wid = t >> 5, lane = t & 31;
    int wm = wid & 3;            // 4 warps in M: 32 rows each
    int wn = wid >> 2;           // 2 warps in N: 64 cols each
    int m0 = blockIdx.x * 128;

    int lr = lane >> 2;          // 0..7  fragment row group
    int lc = lane & 3;           // 0..3  fragment col group

    float acc[2][8][4];          // [m-tile 16][n-tile 8][c-frag]
#pragma unroll
    for (int i = 0; i < 2; ++i)
#pragma unroll
        for (int j = 0; j < 8; ++j)
#pragma unroll
            for (int q = 0; q < 4; ++q) acc[i][j][q] = 0.f;

    for (int c = 0; c < 11; ++c) {
        const float* a; const float* w; int ld, kb, kw;
        if (c < 2)      { a = x; ld = 128; kb = c * 64; w = W_self + (size_t)kb * 128; kw = 64; }
        else if (c < 8) { int r = (c - 2) >> 1; int h = (c - 2) & 1;
                          a = g_A + (size_t)r * N_NODES * 128; ld = 128; kb = h * 64;
                          w = W_rel + (size_t)r * 128 * 128 + (size_t)kb * 128; kw = 64; }
        else            { int r = c - 8;
                          a = g_E + (size_t)r * N_NODES * 16; ld = 16; kb = 0;
                          w = We_rel + (size_t)r * 16 * 128; kw = 16; }

        // ── load+split A tile: 128 rows x kw cols. thread = (row, half of 64)
        {
            int row = t >> 1, half = t & 1;
            int gr = m0 + row;
            const float* ap = a + (size_t)gr * ld + kb + half * 32;
#pragma unroll
            for (int c0 = 0; c0 < 32; c0 += 8) {
                int col = half * 32 + c0;
                if (col < kw) {
                    float f[8];
                    if (gr < N_NODES) {
                        float4 v0 = *reinterpret_cast<const float4*>(ap + c0);
                        float4 v1 = *reinterpret_cast<const float4*>(ap + c0 + 4);
                        f[0]=v0.x; f[1]=v0.y; f[2]=v0.z; f[3]=v0.w;
                        f[4]=v1.x; f[5]=v1.y; f[6]=v1.z; f[7]=v1.w;
                    } else {
#pragma unroll
                        for (int j = 0; j < 8; ++j) f[j] = 0.f;
                    }
                    uint4 hi, lo; split8(f, hi, lo);
                    *reinterpret_cast<uint4*>(sAH + row * KPAD + col) = hi;
                    *reinterpret_cast<uint4*>(sAL + row * KPAD + col) = lo;
                }
            }
        }
        // ── load+split+transpose B tile: sB[n][k], n=0..127, k<kw
#pragma unroll
        for (int i = 0; i < 4; ++i) {
            int task = t + i * 256;
            int n = task >> 3, k0 = (task & 7) * 8;
            if (k0 < kw) {
                float f[8];
#pragma unroll
                for (int j = 0; j < 8; ++j) f[j] = w[(size_t)(k0 + j) * 128 + n];
                uint4 hi, lo; split8(f, hi, lo);
                *reinterpret_cast<uint4*>(sBH + n * KPAD + k0) = hi;
                *reinterpret_cast<uint4*>(sBL + n * KPAD + k0) = lo;
            }
        }
        __syncthreads();

        // ── MMA: 3 combos (AhBh, AlBh, AhBl) over kw/16 k-steps
        int nk = kw >> 4;
#pragma unroll
        for (int combo = 0; combo < 3; ++combo) {
            const __nv_bfloat16* As = (combo == 1) ? sAL : sAH;
            const __nv_bfloat16* Bs = (combo == 2) ? sBL : sBH;
            for (int ks = 0; ks < nk; ++ks) {
                int k0 = ks * 16;
                // B fragments for all 8 n-tiles
                uint32_t bf[8][2];
#pragma unroll
                for (int nt = 0; nt < 8; ++nt) {
                    int n = wn * 64 + nt * 8 + lr;
                    const __nv_bfloat16* bp = Bs + n * KPAD + k0 + lc * 2;
                    bf[nt][0] = *reinterpret_cast<const uint32_t*>(bp);
                    bf[nt][1] = *reinterpret_cast<const uint32_t*>(bp + 8);
                }
#pragma unroll
                for (int mt = 0; mt < 2; ++mt) {
                    int row = wm * 32 + mt * 16 + lr;
                    const __nv_bfloat16* a0p = As + row * KPAD + k0 + lc * 2;
                    const __nv_bfloat16* a1p = a0p + 8 * KPAD;
                    uint32_t a0 = *reinterpret_cast<const uint32_t*>(a0p);
                    uint32_t a1 = *reinterpret_cast<const uint32_t*>(a1p);
                    uint32_t a2 = *reinterpret_cast<const uint32_t*>(a0p + 8);
                    uint32_t a3 = *reinterpret_cast<const uint32_t*>(a1p + 8);
#pragma unroll
                    for (int nt = 0; nt < 8; ++nt)
                        mma16816(acc[mt][nt], a0, a1, a2, a3, bf[nt][0], bf[nt][1]);
                }
            }
        }
        __syncthreads();
    }

    // ── epilogue: + bias, relu, store (fragment layout: c0/c1 row lr, c2/c3 row lr+8)
#pragma unroll
    for (int mt = 0; mt < 2; ++mt) {
        int r0 = m0 + wm * 32 + mt * 16 + lr;
        int r1 = r0 + 8;
#pragma unroll
        for (int nt = 0; nt < 8; ++nt) {
            int col = wn * 64 + nt * 8 + lc * 2;
            float b0 = bias[col], b1 = bias[col + 1];
            if (r0 < N_NODES) {
                float2 v;
                v.x = fmaxf(acc[mt][nt][0] + b0, 0.f);
                v.y = fmaxf(acc[mt][nt][1] + b1, 0.f);
                *reinterpret_cast<float2*>(out + (size_t)r0 * 128 + col) = v;
            }
            if (r1 < N_NODES) {
                float2 v;
                v.x = fmaxf(acc[mt][nt][2] + b0, 0.f);
                v.y = fmaxf(acc[mt][nt][3] + b1, 0.f);
                *reinterpret_cast<float2*>(out + (size_t)r1 * 128 + col) = v;
            }
        }
    }
}

// ───────────────────────── launch ─────────────────────────
extern "C" void kernel_launch(void* const* d_in, const int* in_sizes, int n_in,
                              void* d_out, int out_size) {
    const float* x          = (const float*)d_in[0];
    const float* edge_attr  = (const float*)d_in[1];
    const float* W_rel      = (const float*)d_in[2];
    const float* We_rel     = (const float*)d_in[3];
    const float* W_self     = (const float*)d_in[4];
    const float* b          = (const float*)d_in[5];
    const int*   edge_index = (const int*)d_in[6];
    float* out = (float*)d_out;

    static bool attr_set = false;
    if (!attr_set) {
        cudaFuncSetAttribute(gemm_mma_kernel,
                             cudaFuncAttributeMaxDynamicSharedMemorySize, SMEM_TOTAL);
        attr_set = true;
    }

    zero_kernel<<<2048, 256>>>();

    int n_warps = N_REL * N_EDGES;
    int blocks = (n_warps * 32 + 255) / 256;
    scatter_kernel<<<blocks, 256>>>(x, edge_attr, edge_index);

    int gblocks = (N_NODES + 127) / 128;  // 782
    gemm_mma_kernel<<<gblocks, 256, SMEM_TOTAL>>>(x, W_rel, We_rel, W_self, b, out);
}